// round 9
// baseline (speedup 1.0000x reference)
#include <cuda_runtime.h>
#include <cuda_bf16.h>
#include <cstdint>

#define D_MODEL 768
#define NUM_HEADS 12
#define D_K 64
#define BATCH 2
#define SEQ 2048
#define M_ROWS (BATCH * SEQ)   // 4096
#define NX (M_ROWS * D_MODEL)  // 3145728
#define NW (D_MODEL * D_MODEL) // 589824

// ---------------------------------------------------------------------------
// Scratch (__device__ globals; allocation-free rule)
// ---------------------------------------------------------------------------
__device__ __nv_bfloat16 g_xh[3 * NX];   // split q,k,v inputs; slot0 reused for ctx
__device__ __nv_bfloat16 g_xl[3 * NX];
__device__ __nv_bfloat16 g_wh[4 * NW];   // split w_q,w_k,w_v,w_o
__device__ __nv_bfloat16 g_wl[4 * NW];
__device__ __nv_bfloat16 g_qh[NX];
__device__ __nv_bfloat16 g_ql[NX];
__device__ __nv_bfloat16 g_kh[NX];
__device__ __nv_bfloat16 g_kl[NX];
__device__ __nv_bfloat16 g_vh[NX];
__device__ __nv_bfloat16 g_vl[NX];

// ---------------------------------------------------------------------------
// PTX helpers (family-target safe)
// ---------------------------------------------------------------------------
__device__ __forceinline__ uint32_t smem_to_u32(const void* p) {
    uint32_t a;
    asm("{ .reg .u64 t; cvta.to.shared.u64 t, %1; cvt.u32.u64 %0, t; }"
        : "=r"(a) : "l"(p));
    return a;
}
__device__ __forceinline__ void cp_async16(uint32_t dst, const void* src) {
    asm volatile("cp.async.cg.shared.global [%0], [%1], 16;" :: "r"(dst), "l"(src));
}
__device__ __forceinline__ void cp_commit() {
    asm volatile("cp.async.commit_group;" ::: "memory");
}
template <int N>
__device__ __forceinline__ void cp_wait_group() {
    asm volatile("cp.async.wait_group %0;" :: "n"(N) : "memory");
}
__device__ __forceinline__ void ldsm4(uint32_t& r0, uint32_t& r1, uint32_t& r2,
                                      uint32_t& r3, uint32_t addr) {
    asm volatile("ldmatrix.sync.aligned.m8n8.x4.shared.b16 {%0,%1,%2,%3}, [%4];"
                 : "=r"(r0), "=r"(r1), "=r"(r2), "=r"(r3) : "r"(addr));
}
__device__ __forceinline__ void ldsm4t(uint32_t& r0, uint32_t& r1, uint32_t& r2,
                                       uint32_t& r3, uint32_t addr) {
    asm volatile("ldmatrix.sync.aligned.m8n8.x4.trans.shared.b16 {%0,%1,%2,%3}, [%4];"
                 : "=r"(r0), "=r"(r1), "=r"(r2), "=r"(r3) : "r"(addr));
}
__device__ __forceinline__ void mma16816(float* d, const uint32_t* a, const uint32_t* b) {
    asm volatile(
        "mma.sync.aligned.m16n8k16.row.col.f32.bf16.bf16.f32 "
        "{%0,%1,%2,%3}, {%4,%5,%6,%7}, {%8,%9}, {%0,%1,%2,%3};"
        : "+f"(d[0]), "+f"(d[1]), "+f"(d[2]), "+f"(d[3])
        : "r"(a[0]), "r"(a[1]), "r"(a[2]), "r"(a[3]), "r"(b[0]), "r"(b[1]));
}
__device__ __forceinline__ uint32_t pack_bf16(float x, float y) {
    __nv_bfloat16 bx = __float2bfloat16(x), by = __float2bfloat16(y);
    return (uint32_t)__bfloat16_as_ushort(bx) | ((uint32_t)__bfloat16_as_ushort(by) << 16);
}

// ---------------------------------------------------------------------------
// Split fp32 -> (bf16 hi, bf16 lo); z selects source/dest (fused launches)
// ---------------------------------------------------------------------------
__device__ __forceinline__ void split16(const float* __restrict__ x,
                                        __nv_bfloat16* __restrict__ hi,
                                        __nv_bfloat16* __restrict__ lo, int i0)
{
    float4 v[4];
    #pragma unroll
    for (int u = 0; u < 4; u++)
        v[u] = *reinterpret_cast<const float4*>(x + i0 + u * 4);
    #pragma unroll
    for (int u = 0; u < 4; u++) {
        float vs[4] = {v[u].x, v[u].y, v[u].z, v[u].w};
        uint32_t hp[2], lp[2];
        #pragma unroll
        for (int p = 0; p < 2; p++) {
            __nv_bfloat16 h0 = __float2bfloat16(vs[p * 2 + 0]);
            __nv_bfloat16 h1 = __float2bfloat16(vs[p * 2 + 1]);
            __nv_bfloat16 l0 = __float2bfloat16(vs[p * 2 + 0] - __bfloat162float(h0));
            __nv_bfloat16 l1 = __float2bfloat16(vs[p * 2 + 1] - __bfloat162float(h1));
            hp[p] = (uint32_t)__bfloat16_as_ushort(h0) | ((uint32_t)__bfloat16_as_ushort(h1) << 16);
            lp[p] = (uint32_t)__bfloat16_as_ushort(l0) | ((uint32_t)__bfloat16_as_ushort(l1) << 16);
        }
        *reinterpret_cast<uint2*>(hi + i0 + u * 4) = make_uint2(hp[0], hp[1]);
        *reinterpret_cast<uint2*>(lo + i0 + u * 4) = make_uint2(lp[0], lp[1]);
    }
}

__global__ __launch_bounds__(256) void split_w_kernel(
    const float* __restrict__ w0, const float* __restrict__ w1,
    const float* __restrict__ w2, const float* __restrict__ w3)
{
    const int z = blockIdx.y;
    const float* src = (z == 0) ? w0 : (z == 1) ? w1 : (z == 2) ? w2 : w3;
    const int i0 = (blockIdx.x * 256 + threadIdx.x) * 16;
    if (i0 >= NW) return;
    split16(src, g_wh + (size_t)z * NW, g_wl + (size_t)z * NW, i0);
}

__global__ __launch_bounds__(256) void split_x_kernel(
    const float* __restrict__ x0, const float* __restrict__ x1,
    const float* __restrict__ x2)
{
    const int z = blockIdx.y;
    const float* src = (z == 0) ? x0 : (z == 1) ? x1 : x2;
    const int i0 = (blockIdx.x * 256 + threadIdx.x) * 16;
    if (i0 >= NX) return;
    split16(src, g_xh + (size_t)z * NX, g_xl + (size_t)z * NX, i0);
}

// ---------------------------------------------------------------------------
// Fused split-precision GEMM, z-fused over projections.
// acc = Ah@Bh^T + Ah@Bl^T + Al@Bh^T (+bias). 2-stage cp.async, 2 CTAs/SM.
// Stage layout (stride 80B rows): Ah@0, Al@10240, Bh@20480, Bl@30720.
// ---------------------------------------------------------------------------
#define BK 32
#define SMEM_STRIDE 80
#define ARR_BYTES (128 * SMEM_STRIDE)      // 10240
#define STAGE_BYTES (4 * ARR_BYTES)        // 40960
#define GEMM_SMEM (2 * STAGE_BYTES)        // 81920
#define NCHUNK (D_MODEL / BK)              // 24

__global__ __launch_bounds__(256, 2) void gemm_mma(
    const __nv_bfloat16* __restrict__ XH, const __nv_bfloat16* __restrict__ XL,
    const __nv_bfloat16* __restrict__ WH, const __nv_bfloat16* __restrict__ WL,
    const float* __restrict__ b0, const float* __restrict__ b1,
    const float* __restrict__ b2,
    __nv_bfloat16* __restrict__ yh0, __nv_bfloat16* __restrict__ yh1,
    __nv_bfloat16* __restrict__ yh2,
    __nv_bfloat16* __restrict__ yl0, __nv_bfloat16* __restrict__ yl1,
    __nv_bfloat16* __restrict__ yl2,
    float* __restrict__ Yf, float scale0)
{
    extern __shared__ __align__(128) char smem[];
    const uint32_t sb = smem_to_u32(smem);
    const int z    = blockIdx.z;
    const int t    = threadIdx.x;
    const int wid  = t >> 5;
    const int lane = t & 31;
    const int warp_m = wid & 1;
    const int warp_n = wid >> 1;
    const int n0 = blockIdx.x * 128;
    const int m0 = blockIdx.y * 128;

    const __nv_bfloat16* Ah = XH + (size_t)z * NX;
    const __nv_bfloat16* Al = XL + (size_t)z * NX;
    const __nv_bfloat16* Bh = WH + (size_t)z * NW;
    const __nv_bfloat16* Bl = WL + (size_t)z * NW;
    const float* bias = (z == 0) ? b0 : (z == 1) ? b1 : b2;
    __nv_bfloat16* Yh = (z == 0) ? yh0 : (z == 1) ? yh1 : yh2;
    __nv_bfloat16* Yl = (z == 0) ? yl0 : (z == 1) ? yl1 : yl2;
    const float scale = (z == 0) ? scale0 : 1.0f;

    const uint32_t a_off = (uint32_t)(warp_m * 64 + (lane & 15)) * SMEM_STRIDE
                         + (uint32_t)(lane >> 4) * 16;
    const uint32_t b_off = (uint32_t)(warp_n * 32 + (lane & 7) + ((lane >> 4) << 3)) * SMEM_STRIDE
                         + (uint32_t)((lane >> 3) & 1) * 16;

    float acc[4][4][4] = {};

    auto load_chunk = [&](int c, int s) {
        const int k0 = c * BK;
        const uint32_t base = sb + s * STAGE_BYTES;
        #pragma unroll
        for (int i = 0; i < 8; i++) {
            const int e = t + i * 256;
            const int arr = e >> 9;
            const int row = (e >> 2) & 127;
            const int seg = e & 3;
            const __nv_bfloat16* src =
                (arr == 0) ? (Ah + (size_t)(m0 + row) * D_MODEL) :
                (arr == 1) ? (Al + (size_t)(m0 + row) * D_MODEL) :
                (arr == 2) ? (Bh + (size_t)(n0 + row) * D_MODEL) :
                             (Bl + (size_t)(n0 + row) * D_MODEL);
            cp_async16(base + (uint32_t)arr * ARR_BYTES
                            + (uint32_t)(row * SMEM_STRIDE + seg * 16),
                       src + k0 + seg * 8);
        }
        cp_commit();
    };

    load_chunk(0, 0);

    for (int c = 0; c < NCHUNK; c++) {
        __syncthreads();   // all warps done with stage (c+1)&1 from iter c-1
        if (c + 1 < NCHUNK) {
            load_chunk(c + 1, (c + 1) & 1);
            cp_wait_group<1>();
        } else {
            cp_wait_group<0>();
        }
        __syncthreads();   // stage c&1 visible to all

        const uint32_t st = sb + (c & 1) * STAGE_BYTES;

        #pragma unroll
        for (int ks = 0; ks < 2; ks++) {
            uint32_t bh[4][2], bl[4][2];
            #pragma unroll
            for (int p = 0; p < 2; p++) {
                uint32_t r0, r1, r2, r3;
                ldsm4(r0, r1, r2, r3,
                      st + 2 * ARR_BYTES + b_off + p * 16 * SMEM_STRIDE + ks * 32);
                bh[p * 2 + 0][0] = r0; bh[p * 2 + 0][1] = r1;
                bh[p * 2 + 1][0] = r2; bh[p * 2 + 1][1] = r3;
                ldsm4(r0, r1, r2, r3,
                      st + 3 * ARR_BYTES + b_off + p * 16 * SMEM_STRIDE + ks * 32);
                bl[p * 2 + 0][0] = r0; bl[p * 2 + 0][1] = r1;
                bl[p * 2 + 1][0] = r2; bl[p * 2 + 1][1] = r3;
            }
            {
                uint32_t af[4][4];
                #pragma unroll
                for (int mt = 0; mt < 4; mt++)
                    ldsm4(af[mt][0], af[mt][1], af[mt][2], af[mt][3],
                          st + a_off + mt * 16 * SMEM_STRIDE + ks * 32);
                #pragma unroll
                for (int mt = 0; mt < 4; mt++)
                    #pragma unroll
                    for (int nt = 0; nt < 4; nt++) {
                        mma16816(acc[mt][nt], af[mt], bh[nt]);
                        mma16816(acc[mt][nt], af[mt], bl[nt]);
                    }
            }
            {
                uint32_t al[4][4];
                #pragma unroll
                for (int mt = 0; mt < 4; mt++)
                    ldsm4(al[mt][0], al[mt][1], al[mt][2], al[mt][3],
                          st + ARR_BYTES + a_off + mt * 16 * SMEM_STRIDE + ks * 32);
                #pragma unroll
                for (int mt = 0; mt < 4; mt++)
                    #pragma unroll
                    for (int nt = 0; nt < 4; nt++)
                        mma16816(acc[mt][nt], al[mt], bh[nt]);
            }
        }
    }

    const int colb = n0 + warp_n * 32 + (lane & 3) * 2;
    const int rowb = m0 + warp_m * 64 + (lane >> 2);
    #pragma unroll
    for (int nt = 0; nt < 4; nt++) {
        const int col = colb + nt * 8;
        const float2 bv = *reinterpret_cast<const float2*>(&bias[col]);
        #pragma unroll
        for (int mt = 0; mt < 4; mt++) {
            const int r0 = rowb + mt * 16;
            float o00 = acc[mt][nt][0] + bv.x, o01 = acc[mt][nt][1] + bv.y;
            float o10 = acc[mt][nt][2] + bv.x, o11 = acc[mt][nt][3] + bv.y;
            if (Yf) {
                *reinterpret_cast<float2*>(&Yf[(size_t)r0 * D_MODEL + col]) = make_float2(o00, o01);
                *reinterpret_cast<float2*>(&Yf[(size_t)(r0 + 8) * D_MODEL + col]) = make_float2(o10, o11);
            } else {
                o00 *= scale; o01 *= scale; o10 *= scale; o11 *= scale;
                __nv_bfloat16 h00 = __float2bfloat16(o00), h01 = __float2bfloat16(o01);
                __nv_bfloat16 h10 = __float2bfloat16(o10), h11 = __float2bfloat16(o11);
                uint32_t hp0 = (uint32_t)__bfloat16_as_ushort(h00) | ((uint32_t)__bfloat16_as_ushort(h01) << 16);
                uint32_t hp1 = (uint32_t)__bfloat16_as_ushort(h10) | ((uint32_t)__bfloat16_as_ushort(h11) << 16);
                uint32_t lp0 = pack_bf16(o00 - __bfloat162float(h00), o01 - __bfloat162float(h01));
                uint32_t lp1 = pack_bf16(o10 - __bfloat162float(h10), o11 - __bfloat162float(h11));
                *reinterpret_cast<uint32_t*>(&Yh[(size_t)r0 * D_MODEL + col]) = hp0;
                *reinterpret_cast<uint32_t*>(&Yh[(size_t)(r0 + 8) * D_MODEL + col]) = hp1;
                *reinterpret_cast<uint32_t*>(&Yl[(size_t)r0 * D_MODEL + col]) = lp0;
                *reinterpret_cast<uint32_t*>(&Yl[(size_t)(r0 + 8) * D_MODEL + col]) = lp1;
            }
        }
    }
}

// ---------------------------------------------------------------------------
// FA2-style attention, mma.sync bf16 3-term split (unchanged, proven).
// ---------------------------------------------------------------------------
#define AT_RS 144
#define AT_Q_BYTES (128 * AT_RS)
#define AT_ARR (64 * AT_RS)
#define AT_STAGE (4 * AT_ARR)
#define AT_KV_BASE (2 * AT_Q_BYTES)
#define AT_SMEM (AT_KV_BASE + 3 * AT_STAGE)
#define NKV (SEQ / 64)

__global__ __launch_bounds__(256, 1) void attn_mma(
    const __nv_bfloat16* __restrict__ qh, const __nv_bfloat16* __restrict__ ql,
    const __nv_bfloat16* __restrict__ kh, const __nv_bfloat16* __restrict__ kl,
    const __nv_bfloat16* __restrict__ vh, const __nv_bfloat16* __restrict__ vl,
    __nv_bfloat16* __restrict__ Ch, __nv_bfloat16* __restrict__ Cl)
{
    extern __shared__ __align__(128) char smem[];
    const uint32_t sb = smem_to_u32(smem);
    const int t    = threadIdx.x;
    const int wid  = t >> 5;
    const int lane = t & 31;
    const int b  = blockIdx.z;
    const int h  = blockIdx.y;
    const int q0 = blockIdx.x * 128;

    const size_t base = (size_t)b * SEQ * D_MODEL + h * D_K;
    const __nv_bfloat16* Qh_g = qh + base + (size_t)q0 * D_MODEL;
    const __nv_bfloat16* Ql_g = ql + base + (size_t)q0 * D_MODEL;
    const __nv_bfloat16* Kh_g = kh + base;
    const __nv_bfloat16* Kl_g = kl + base;
    const __nv_bfloat16* Vh_g = vh + base;
    const __nv_bfloat16* Vl_g = vl + base;

    #pragma unroll
    for (int i = 0; i < 4; i++) {
        int e = t + i * 256;
        int row = e >> 3, seg = e & 7;
        uint32_t d = (uint32_t)(row * AT_RS + seg * 16);
        cp_async16(sb + d, Qh_g + (size_t)row * D_MODEL + seg * 8);
        cp_async16(sb + AT_Q_BYTES + d, Ql_g + (size_t)row * D_MODEL + seg * 8);
    }
    cp_commit();

    auto loadkv = [&](int c, int s) {
        const uint32_t st = sb + AT_KV_BASE + s * AT_STAGE;
        #pragma unroll
        for (int i = 0; i < 8; i++) {
            int e = t + i * 256;
            int arr = e >> 9, row = (e >> 3) & 63, seg = e & 7;
            const __nv_bfloat16* src =
                (arr == 0) ? Kh_g : (arr == 1) ? Kl_g : (arr == 2) ? Vh_g : Vl_g;
            cp_async16(st + arr * AT_ARR + (uint32_t)(row * AT_RS + seg * 16),
                       src + (size_t)(c * 64 + row) * D_MODEL + seg * 8);
        }
        cp_commit();
    };

    loadkv(0, 0);
    loadkv(1, 1);

    cp_wait_group<2>();
    __syncthreads();
    uint32_t qfh[4][4], qfl[4][4];
    {
        const uint32_t ab = sb + (uint32_t)(wid * 16 + (lane & 15)) * AT_RS
                          + (uint32_t)(lane >> 4) * 16;
        #pragma unroll
        for (int kk = 0; kk < 4; kk++) {
            ldsm4(qfh[kk][0], qfh[kk][1], qfh[kk][2], qfh[kk][3], ab + kk * 32);
            ldsm4(qfl[kk][0], qfl[kk][1], qfl[kk][2], qfl[kk][3], ab + AT_Q_BYTES + kk * 32);
        }
    }

    float accO[8][4] = {};
    float m0r = -1e30f, m1r = -1e30f, l0 = 0.f, l1 = 0.f;

    const uint32_t bb_off = (uint32_t)((lane & 7) + ((lane >> 4) << 3)) * AT_RS
                          + (uint32_t)((lane >> 3) & 1) * 16;
    const uint32_t vb_off = (uint32_t)(lane & 15) * AT_RS + (uint32_t)(lane >> 4) * 16;

    for (int c = 0; c < NKV; c++) {
        if (c + 1 < NKV) cp_wait_group<1>(); else cp_wait_group<0>();
        __syncthreads();
        if (c + 2 < NKV) loadkv(c + 2, (c + 2) % 3);

        const uint32_t st = sb + AT_KV_BASE + (c % 3) * AT_STAGE;

        float s[8][4] = {};
        #pragma unroll
        for (int kk = 0; kk < 4; kk++) {
            const uint32_t bk = st + bb_off + kk * 32;
            #pragma unroll
            for (int g = 0; g < 4; g++) {
                uint32_t r0, r1, r2, r3;
                ldsm4(r0, r1, r2, r3, bk + (uint32_t)g * 16 * AT_RS);
                uint32_t bh0[2] = {r0, r1}, bh1[2] = {r2, r3};
                mma16816(s[g * 2 + 0], qfh[kk], bh0);
                mma16816(s[g * 2 + 1], qfh[kk], bh1);
                mma16816(s[g * 2 + 0], qfl[kk], bh0);
                mma16816(s[g * 2 + 1], qfl[kk], bh1);
                ldsm4(r0, r1, r2, r3, bk + AT_ARR + (uint32_t)g * 16 * AT_RS);
                uint32_t bl0[2] = {r0, r1}, bl1[2] = {r2, r3};
                mma16816(s[g * 2 + 0], qfh[kk], bl0);
                mma16816(s[g * 2 + 1], qfh[kk], bl1);
            }
        }

        float mx0 = s[0][0], mx1 = s[0][2];
        #pragma unroll
        for (int j = 0; j < 8; j++) {
            mx0 = fmaxf(mx0, fmaxf(s[j][0], s[j][1]));
            mx1 = fmaxf(mx1, fmaxf(s[j][2], s[j][3]));
        }
        mx0 = fmaxf(mx0, __shfl_xor_sync(0xffffffffu, mx0, 1));
        mx0 = fmaxf(mx0, __shfl_xor_sync(0xffffffffu, mx0, 2));
        mx1 = fmaxf(mx1, __shfl_xor_sync(0xffffffffu, mx1, 1));
        mx1 = fmaxf(mx1, __shfl_xor_sync(0xffffffffu, mx1, 2));

        const float mn0 = fmaxf(m0r, mx0), mn1 = fmaxf(m1r, mx1);
        const float al0 = __expf(m0r - mn0), al1 = __expf(m1r - mn1);
        m0r = mn0; m1r = mn1;

        float rs0 = 0.f, rs1 = 0.f;
        #pragma unroll
        for (int j = 0; j < 8; j++) {
            s[j][0] = __expf(s[j][0] - mn0);
            s[j][1] = __expf(s[j][1] - mn0);
            s[j][2] = __expf(s[j][2] - mn1);
            s[j][3] = __expf(s[j][3] - mn1);
            rs0 += s[j][0] + s[j][1];
            rs1 += s[j][2] + s[j][3];
        }
        rs0 += __shfl_xor_sync(0xffffffffu, rs0, 1);
        rs0 += __shfl_xor_sync(0xffffffffu, rs0, 2);
        rs1 += __shfl_xor_sync(0xffffffffu, rs1, 1);
        rs1 += __shfl_xor_sync(0xffffffffu, rs1, 2);
        l0 = l0 * al0 + rs0;
        l1 = l1 * al1 + rs1;

        #pragma unroll
        for (int nt = 0; nt < 8; nt++) {
            accO[nt][0] *= al0; accO[nt][1] *= al0;
            accO[nt][2] *= al1; accO[nt][3] *= al1;
        }

        uint32_t ph[4][4], pl[4][4];
        #pragma unroll
        for (int kk = 0; kk < 4; kk++) {
            const int j0 = 2 * kk, j1 = 2 * kk + 1;
            float v00 = s[j0][0], v01 = s[j0][1], v02 = s[j0][2], v03 = s[j0][3];
            float v10 = s[j1][0], v11 = s[j1][1], v12 = s[j1][2], v13 = s[j1][3];
            __nv_bfloat16 h;
            float r00, r01, r02, r03, r10, r11, r12, r13;
            h = __float2bfloat16(v00); r00 = v00 - __bfloat162float(h);
            h = __float2bfloat16(v01); r01 = v01 - __bfloat162float(h);
            h = __float2bfloat16(v02); r02 = v02 - __bfloat162float(h);
            h = __float2bfloat16(v03); r03 = v03 - __bfloat162float(h);
            h = __float2bfloat16(v10); r10 = v10 - __bfloat162float(h);
            h = __float2bfloat16(v11); r11 = v11 - __bfloat162float(h);
            h = __float2bfloat16(v12); r12 = v12 - __bfloat162float(h);
            h = __float2bfloat16(v13); r13 = v13 - __bfloat162float(h);
            ph[kk][0] = pack_bf16(v00, v01);
            ph[kk][1] = pack_bf16(v02, v03);
            ph[kk][2] = pack_bf16(v10, v11);
            ph[kk][3] = pack_bf16(v12, v13);
            pl[kk][0] = pack_bf16(r00, r01);
            pl[kk][1] = pack_bf16(r02, r03);
            pl[kk][2] = pack_bf16(r10, r11);
            pl[kk][3] = pack_bf16(r12, r13);
        }

        const uint32_t vst = st + 2 * AT_ARR;
        #pragma unroll
        for (int kk = 0; kk < 4; kk++) {
            const uint32_t vk = vst + vb_off + (uint32_t)(kk * 16) * AT_RS;
            #pragma unroll
            for (int np = 0; np < 4; np++) {
                uint32_t r0, r1, r2, r3;
                ldsm4t(r0, r1, r2, r3, vk + np * 32);
                uint32_t b0[2] = {r0, r1}, b1[2] = {r2, r3};
                mma16816(accO[np * 2 + 0], ph[kk], b0);
                mma16816(accO[np * 2 + 1], ph[kk], b1);
                mma16816(accO[np * 2 + 0], pl[kk], b0);
                mma16816(accO[np * 2 + 1], pl[kk], b1);
                ldsm4t(r0, r1, r2, r3, vk + AT_ARR + np * 32);
                uint32_t c0[2] = {r0, r1}, c1[2] = {r2, r3};
                mma16816(accO[np * 2 + 0], ph[kk], c0);
                mma16816(accO[np * 2 + 1], ph[kk], c1);
            }
        }
    }

    const float inv0 = 1.0f / l0, inv1 = 1.0f / l1;
    const int r0g = q0 + wid * 16 + (lane >> 2);
    const size_t orow0 = ((size_t)b * SEQ + r0g) * D_MODEL + h * D_K;
    const size_t orow1 = orow0 + 8 * D_MODEL;
    #pragma unroll
    for (int nt = 0; nt < 8; nt++) {
        const int col = nt * 8 + (lane & 3) * 2;
        float o00 = accO[nt][0] * inv0, o01 = accO[nt][1] * inv0;
        float o10 = accO[nt][2] * inv1, o11 = accO[nt][3] * inv1;
        __nv_bfloat16 h00 = __float2bfloat16(o00), h01 = __float2bfloat16(o01);
        __nv_bfloat16 h10 = __float2bfloat16(o10), h11 = __float2bfloat16(o11);
        uint32_t hp0 = (uint32_t)__bfloat16_as_ushort(h00) | ((uint32_t)__bfloat16_as_ushort(h01) << 16);
        uint32_t hp1 = (uint32_t)__bfloat16_as_ushort(h10) | ((uint32_t)__bfloat16_as_ushort(h11) << 16);
        uint32_t lp0 = pack_bf16(o00 - __bfloat162float(h00), o01 - __bfloat162float(h01));
        uint32_t lp1 = pack_bf16(o10 - __bfloat162float(h10), o11 - __bfloat162float(h11));
        *reinterpret_cast<uint32_t*>(&Ch[orow0 + col]) = hp0;
        *reinterpret_cast<uint32_t*>(&Ch[orow1 + col]) = hp1;
        *reinterpret_cast<uint32_t*>(&Cl[orow0 + col]) = lp0;
        *reinterpret_cast<uint32_t*>(&Cl[orow1 + col]) = lp1;
    }
}

// ---------------------------------------------------------------------------
// Launch
// ---------------------------------------------------------------------------
extern "C" void kernel_launch(void* const* d_in, const int* in_sizes, int n_in,
                              void* d_out, int out_size)
{
    const float* q   = (const float*)d_in[0];
    const float* k   = (const float*)d_in[1];
    const float* v   = (const float*)d_in[2];
    const float* w_q = (const float*)d_in[3];
    const float* b_q = (const float*)d_in[4];
    const float* w_k = (const float*)d_in[5];
    const float* b_k = (const float*)d_in[6];
    const float* w_v = (const float*)d_in[7];
    const float* b_v = (const float*)d_in[8];
    const float* w_o = (const float*)d_in[9];
    const float* b_o = (const float*)d_in[10];
    float* out = (float*)d_out;

    __nv_bfloat16 *xh, *xl, *wh, *wl, *qh, *ql, *kh, *kl, *vh, *vl;
    cudaGetSymbolAddress((void**)&xh, g_xh);
    cudaGetSymbolAddress((void**)&xl, g_xl);
    cudaGetSymbolAddress((void**)&wh, g_wh);
    cudaGetSymbolAddress((void**)&wl, g_wl);
    cudaGetSymbolAddress((void**)&qh, g_qh);
    cudaGetSymbolAddress((void**)&ql, g_ql);
    cudaGetSymbolAddress((void**)&kh, g_kh);
    cudaGetSymbolAddress((void**)&kl, g_kl);
    cudaGetSymbolAddress((void**)&vh, g_vh);
    cudaGetSymbolAddress((void**)&vl, g_vl);

    cudaFuncSetAttribute(gemm_mma,
                         cudaFuncAttributeMaxDynamicSharedMemorySize, GEMM_SMEM);
    cudaFuncSetAttribute(attn_mma,
                         cudaFuncAttributeMaxDynamicSharedMemorySize, AT_SMEM);

    const int gx = NX / 16 / 256;               // 768
    const int gw = NW / 16 / 256;               // 144

    // All splits up front (2 launches)
    split_w_kernel<<<dim3(gw, 4), 256>>>(w_q, w_k, w_v, w_o);
    split_x_kernel<<<dim3(gx, 3), 256>>>(q, k, v);

    // Fused Q/K/V projections (z = 0,1,2); scale folded into Q
    dim3 qkv_grid(D_MODEL / 128, M_ROWS / 128, 3);  // (6, 32, 3)
    gemm_mma<<<qkv_grid, 256, GEMM_SMEM>>>(
        xh, xl, wh, wl, b_q, b_k, b_v,
        qh, kh, vh, ql, kl, vl, nullptr, 0.125f);

    // Attention (writes split ctx into x slot 0)
    dim3 attn_grid(SEQ / 128, NUM_HEADS, BATCH);  // (16, 12, 2)
    attn_mma<<<attn_grid, 256, AT_SMEM>>>(qh, ql, kh, kl, vh, vl, xh, xl);

    // Output projection (weight slot 3) -> fp32 out
    dim3 out_grid(D_MODEL / 128, M_ROWS / 128, 1);
    gemm_mma<<<out_grid, 256, GEMM_SMEM>>>(
        xh, xl, wh + (size_t)3 * NW, wl + (size_t)3 * NW, b_o, b_o, b_o,
        nullptr, nullptr, nullptr, nullptr, nullptr, nullptr, out, 1.0f);
}

// round 10
// speedup vs baseline: 1.0002x; 1.0002x over previous
#include <cuda_runtime.h>
#include <cuda_bf16.h>
#include <cstdint>

#define D_MODEL 768
#define NUM_HEADS 12
#define D_K 64
#define BATCH 2
#define SEQ 2048
#define M_ROWS (BATCH * SEQ)   // 4096
#define NX (M_ROWS * D_MODEL)  // 3145728
#define NW (D_MODEL * D_MODEL) // 589824

// ---------------------------------------------------------------------------
// Scratch (__device__ globals; allocation-free rule)
// ---------------------------------------------------------------------------
__device__ __nv_bfloat16 g_xh[3 * NX];   // split q,k,v inputs; slot0 reused for ctx
__device__ __nv_bfloat16 g_xl[3 * NX];
__device__ __nv_bfloat16 g_wh[4 * NW];   // split w_q,w_k,w_v,w_o
__device__ __nv_bfloat16 g_wl[4 * NW];
__device__ __nv_bfloat16 g_qh[NX];
__device__ __nv_bfloat16 g_ql[NX];
__device__ __nv_bfloat16 g_kh[NX];
__device__ __nv_bfloat16 g_kl[NX];
__device__ __nv_bfloat16 g_vh[NX];
__device__ __nv_bfloat16 g_vl[NX];

// ---------------------------------------------------------------------------
// PTX helpers (family-target safe)
// ---------------------------------------------------------------------------
__device__ __forceinline__ uint32_t smem_to_u32(const void* p) {
    uint32_t a;
    asm("{ .reg .u64 t; cvta.to.shared.u64 t, %1; cvt.u32.u64 %0, t; }"
        : "=r"(a) : "l"(p));
    return a;
}
__device__ __forceinline__ void cp_async16(uint32_t dst, const void* src) {
    asm volatile("cp.async.cg.shared.global [%0], [%1], 16;" :: "r"(dst), "l"(src));
}
__device__ __forceinline__ void cp_commit() {
    asm volatile("cp.async.commit_group;" ::: "memory");
}
template <int N>
__device__ __forceinline__ void cp_wait_group() {
    asm volatile("cp.async.wait_group %0;" :: "n"(N) : "memory");
}
__device__ __forceinline__ void ldsm4(uint32_t& r0, uint32_t& r1, uint32_t& r2,
                                      uint32_t& r3, uint32_t addr) {
    asm volatile("ldmatrix.sync.aligned.m8n8.x4.shared.b16 {%0,%1,%2,%3}, [%4];"
                 : "=r"(r0), "=r"(r1), "=r"(r2), "=r"(r3) : "r"(addr));
}
__device__ __forceinline__ void ldsm4t(uint32_t& r0, uint32_t& r1, uint32_t& r2,
                                       uint32_t& r3, uint32_t addr) {
    asm volatile("ldmatrix.sync.aligned.m8n8.x4.trans.shared.b16 {%0,%1,%2,%3}, [%4];"
                 : "=r"(r0), "=r"(r1), "=r"(r2), "=r"(r3) : "r"(addr));
}
__device__ __forceinline__ void mma16816(float* d, const uint32_t* a, const uint32_t* b) {
    asm volatile(
        "mma.sync.aligned.m16n8k16.row.col.f32.bf16.bf16.f32 "
        "{%0,%1,%2,%3}, {%4,%5,%6,%7}, {%8,%9}, {%0,%1,%2,%3};"
        : "+f"(d[0]), "+f"(d[1]), "+f"(d[2]), "+f"(d[3])
        : "r"(a[0]), "r"(a[1]), "r"(a[2]), "r"(a[3]), "r"(b[0]), "r"(b[1]));
}
__device__ __forceinline__ uint32_t pack_bf16(float x, float y) {
    __nv_bfloat16 bx = __float2bfloat16(x), by = __float2bfloat16(y);
    return (uint32_t)__bfloat16_as_ushort(bx) | ((uint32_t)__bfloat16_as_ushort(by) << 16);
}

// ---------------------------------------------------------------------------
// Split fp32 -> (bf16 hi, bf16 lo); z selects source/dest (fused launches)
// ---------------------------------------------------------------------------
__device__ __forceinline__ void split16(const float* __restrict__ x,
                                        __nv_bfloat16* __restrict__ hi,
                                        __nv_bfloat16* __restrict__ lo, int i0)
{
    float4 v[4];
    #pragma unroll
    for (int u = 0; u < 4; u++)
        v[u] = *reinterpret_cast<const float4*>(x + i0 + u * 4);
    #pragma unroll
    for (int u = 0; u < 4; u++) {
        float vs[4] = {v[u].x, v[u].y, v[u].z, v[u].w};
        uint32_t hp[2], lp[2];
        #pragma unroll
        for (int p = 0; p < 2; p++) {
            __nv_bfloat16 h0 = __float2bfloat16(vs[p * 2 + 0]);
            __nv_bfloat16 h1 = __float2bfloat16(vs[p * 2 + 1]);
            __nv_bfloat16 l0 = __float2bfloat16(vs[p * 2 + 0] - __bfloat162float(h0));
            __nv_bfloat16 l1 = __float2bfloat16(vs[p * 2 + 1] - __bfloat162float(h1));
            hp[p] = (uint32_t)__bfloat16_as_ushort(h0) | ((uint32_t)__bfloat16_as_ushort(h1) << 16);
            lp[p] = (uint32_t)__bfloat16_as_ushort(l0) | ((uint32_t)__bfloat16_as_ushort(l1) << 16);
        }
        *reinterpret_cast<uint2*>(hi + i0 + u * 4) = make_uint2(hp[0], hp[1]);
        *reinterpret_cast<uint2*>(lo + i0 + u * 4) = make_uint2(lp[0], lp[1]);
    }
}

__global__ __launch_bounds__(256) void split_w_kernel(
    const float* __restrict__ w0, const float* __restrict__ w1,
    const float* __restrict__ w2, const float* __restrict__ w3)
{
    const int z = blockIdx.y;
    const float* src = (z == 0) ? w0 : (z == 1) ? w1 : (z == 2) ? w2 : w3;
    const int i0 = (blockIdx.x * 256 + threadIdx.x) * 16;
    if (i0 >= NW) return;
    split16(src, g_wh + (size_t)z * NW, g_wl + (size_t)z * NW, i0);
}

__global__ __launch_bounds__(256) void split_x_kernel(
    const float* __restrict__ x0, const float* __restrict__ x1,
    const float* __restrict__ x2)
{
    const int z = blockIdx.y;
    const float* src = (z == 0) ? x0 : (z == 1) ? x1 : x2;
    const int i0 = (blockIdx.x * 256 + threadIdx.x) * 16;
    if (i0 >= NX) return;
    split16(src, g_xh + (size_t)z * NX, g_xl + (size_t)z * NX, i0);
}

// ---------------------------------------------------------------------------
// Fused split-precision GEMM, z-fused over projections.
// acc = Ah@Bh^T + Ah@Bl^T + Al@Bh^T (+bias). 2-stage cp.async, 2 CTAs/SM.
// Stage layout (stride 80B rows): Ah@0, Al@10240, Bh@20480, Bl@30720.
// ---------------------------------------------------------------------------
#define BK 32
#define SMEM_STRIDE 80
#define ARR_BYTES (128 * SMEM_STRIDE)      // 10240
#define STAGE_BYTES (4 * ARR_BYTES)        // 40960
#define GEMM_SMEM (2 * STAGE_BYTES)        // 81920
#define NCHUNK (D_MODEL / BK)              // 24

__global__ __launch_bounds__(256, 2) void gemm_mma(
    const __nv_bfloat16* __restrict__ XH, const __nv_bfloat16* __restrict__ XL,
    const __nv_bfloat16* __restrict__ WH, const __nv_bfloat16* __restrict__ WL,
    const float* __restrict__ b0, const float* __restrict__ b1,
    const float* __restrict__ b2,
    __nv_bfloat16* __restrict__ yh0, __nv_bfloat16* __restrict__ yh1,
    __nv_bfloat16* __restrict__ yh2,
    __nv_bfloat16* __restrict__ yl0, __nv_bfloat16* __restrict__ yl1,
    __nv_bfloat16* __restrict__ yl2,
    float* __restrict__ Yf, float scale0)
{
    extern __shared__ __align__(128) char smem[];
    const uint32_t sb = smem_to_u32(smem);
    const int z    = blockIdx.z;
    const int t    = threadIdx.x;
    const int wid  = t >> 5;
    const int lane = t & 31;
    const int warp_m = wid & 1;
    const int warp_n = wid >> 1;
    const int n0 = blockIdx.x * 128;
    const int m0 = blockIdx.y * 128;

    const __nv_bfloat16* Ah = XH + (size_t)z * NX;
    const __nv_bfloat16* Al = XL + (size_t)z * NX;
    const __nv_bfloat16* Bh = WH + (size_t)z * NW;
    const __nv_bfloat16* Bl = WL + (size_t)z * NW;
    const float* bias = (z == 0) ? b0 : (z == 1) ? b1 : b2;
    __nv_bfloat16* Yh = (z == 0) ? yh0 : (z == 1) ? yh1 : yh2;
    __nv_bfloat16* Yl = (z == 0) ? yl0 : (z == 1) ? yl1 : yl2;
    const float scale = (z == 0) ? scale0 : 1.0f;

    const uint32_t a_off = (uint32_t)(warp_m * 64 + (lane & 15)) * SMEM_STRIDE
                         + (uint32_t)(lane >> 4) * 16;
    const uint32_t b_off = (uint32_t)(warp_n * 32 + (lane & 7) + ((lane >> 4) << 3)) * SMEM_STRIDE
                         + (uint32_t)((lane >> 3) & 1) * 16;

    float acc[4][4][4] = {};

    auto load_chunk = [&](int c, int s) {
        const int k0 = c * BK;
        const uint32_t base = sb + s * STAGE_BYTES;
        #pragma unroll
        for (int i = 0; i < 8; i++) {
            const int e = t + i * 256;
            const int arr = e >> 9;
            const int row = (e >> 2) & 127;
            const int seg = e & 3;
            const __nv_bfloat16* src =
                (arr == 0) ? (Ah + (size_t)(m0 + row) * D_MODEL) :
                (arr == 1) ? (Al + (size_t)(m0 + row) * D_MODEL) :
                (arr == 2) ? (Bh + (size_t)(n0 + row) * D_MODEL) :
                             (Bl + (size_t)(n0 + row) * D_MODEL);
            cp_async16(base + (uint32_t)arr * ARR_BYTES
                            + (uint32_t)(row * SMEM_STRIDE + seg * 16),
                       src + k0 + seg * 8);
        }
        cp_commit();
    };

    load_chunk(0, 0);

    for (int c = 0; c < NCHUNK; c++) {
        __syncthreads();   // all warps done with stage (c+1)&1 from iter c-1
        if (c + 1 < NCHUNK) {
            load_chunk(c + 1, (c + 1) & 1);
            cp_wait_group<1>();
        } else {
            cp_wait_group<0>();
        }
        __syncthreads();   // stage c&1 visible to all

        const uint32_t st = sb + (c & 1) * STAGE_BYTES;

        #pragma unroll
        for (int ks = 0; ks < 2; ks++) {
            uint32_t bh[4][2], bl[4][2];
            #pragma unroll
            for (int p = 0; p < 2; p++) {
                uint32_t r0, r1, r2, r3;
                ldsm4(r0, r1, r2, r3,
                      st + 2 * ARR_BYTES + b_off + p * 16 * SMEM_STRIDE + ks * 32);
                bh[p * 2 + 0][0] = r0; bh[p * 2 + 0][1] = r1;
                bh[p * 2 + 1][0] = r2; bh[p * 2 + 1][1] = r3;
                ldsm4(r0, r1, r2, r3,
                      st + 3 * ARR_BYTES + b_off + p * 16 * SMEM_STRIDE + ks * 32);
                bl[p * 2 + 0][0] = r0; bl[p * 2 + 0][1] = r1;
                bl[p * 2 + 1][0] = r2; bl[p * 2 + 1][1] = r3;
            }
            {
                uint32_t af[4][4];
                #pragma unroll
                for (int mt = 0; mt < 4; mt++)
                    ldsm4(af[mt][0], af[mt][1], af[mt][2], af[mt][3],
                          st + a_off + mt * 16 * SMEM_STRIDE + ks * 32);
                #pragma unroll
                for (int mt = 0; mt < 4; mt++)
                    #pragma unroll
                    for (int nt = 0; nt < 4; nt++) {
                        mma16816(acc[mt][nt], af[mt], bh[nt]);
                        mma16816(acc[mt][nt], af[mt], bl[nt]);
                    }
            }
            {
                uint32_t al[4][4];
                #pragma unroll
                for (int mt = 0; mt < 4; mt++)
                    ldsm4(al[mt][0], al[mt][1], al[mt][2], al[mt][3],
                          st + ARR_BYTES + a_off + mt * 16 * SMEM_STRIDE + ks * 32);
                #pragma unroll
                for (int mt = 0; mt < 4; mt++)
                    #pragma unroll
                    for (int nt = 0; nt < 4; nt++)
                        mma16816(acc[mt][nt], al[mt], bh[nt]);
            }
        }
    }

    const int colb = n0 + warp_n * 32 + (lane & 3) * 2;
    const int rowb = m0 + warp_m * 64 + (lane >> 2);
    #pragma unroll
    for (int nt = 0; nt < 4; nt++) {
        const int col = colb + nt * 8;
        const float2 bv = *reinterpret_cast<const float2*>(&bias[col]);
        #pragma unroll
        for (int mt = 0; mt < 4; mt++) {
            const int r0 = rowb + mt * 16;
            float o00 = acc[mt][nt][0] + bv.x, o01 = acc[mt][nt][1] + bv.y;
            float o10 = acc[mt][nt][2] + bv.x, o11 = acc[mt][nt][3] + bv.y;
            if (Yf) {
                *reinterpret_cast<float2*>(&Yf[(size_t)r0 * D_MODEL + col]) = make_float2(o00, o01);
                *reinterpret_cast<float2*>(&Yf[(size_t)(r0 + 8) * D_MODEL + col]) = make_float2(o10, o11);
            } else {
                o00 *= scale; o01 *= scale; o10 *= scale; o11 *= scale;
                __nv_bfloat16 h00 = __float2bfloat16(o00), h01 = __float2bfloat16(o01);
                __nv_bfloat16 h10 = __float2bfloat16(o10), h11 = __float2bfloat16(o11);
                uint32_t hp0 = (uint32_t)__bfloat16_as_ushort(h00) | ((uint32_t)__bfloat16_as_ushort(h01) << 16);
                uint32_t hp1 = (uint32_t)__bfloat16_as_ushort(h10) | ((uint32_t)__bfloat16_as_ushort(h11) << 16);
                uint32_t lp0 = pack_bf16(o00 - __bfloat162float(h00), o01 - __bfloat162float(h01));
                uint32_t lp1 = pack_bf16(o10 - __bfloat162float(h10), o11 - __bfloat162float(h11));
                *reinterpret_cast<uint32_t*>(&Yh[(size_t)r0 * D_MODEL + col]) = hp0;
                *reinterpret_cast<uint32_t*>(&Yh[(size_t)(r0 + 8) * D_MODEL + col]) = hp1;
                *reinterpret_cast<uint32_t*>(&Yl[(size_t)r0 * D_MODEL + col]) = lp0;
                *reinterpret_cast<uint32_t*>(&Yl[(size_t)(r0 + 8) * D_MODEL + col]) = lp1;
            }
        }
    }
}

// ---------------------------------------------------------------------------
// FA2-style attention, mma.sync bf16 3-term split (unchanged, proven).
// ---------------------------------------------------------------------------
#define AT_RS 144
#define AT_Q_BYTES (128 * AT_RS)
#define AT_ARR (64 * AT_RS)
#define AT_STAGE (4 * AT_ARR)
#define AT_KV_BASE (2 * AT_Q_BYTES)
#define AT_SMEM (AT_KV_BASE + 3 * AT_STAGE)
#define NKV (SEQ / 64)

__global__ __launch_bounds__(256, 1) void attn_mma(
    const __nv_bfloat16* __restrict__ qh, const __nv_bfloat16* __restrict__ ql,
    const __nv_bfloat16* __restrict__ kh, const __nv_bfloat16* __restrict__ kl,
    const __nv_bfloat16* __restrict__ vh, const __nv_bfloat16* __restrict__ vl,
    __nv_bfloat16* __restrict__ Ch, __nv_bfloat16* __restrict__ Cl)
{
    extern __shared__ __align__(128) char smem[];
    const uint32_t sb = smem_to_u32(smem);
    const int t    = threadIdx.x;
    const int wid  = t >> 5;
    const int lane = t & 31;
    const int b  = blockIdx.z;
    const int h  = blockIdx.y;
    const int q0 = blockIdx.x * 128;

    const size_t base = (size_t)b * SEQ * D_MODEL + h * D_K;
    const __nv_bfloat16* Qh_g = qh + base + (size_t)q0 * D_MODEL;
    const __nv_bfloat16* Ql_g = ql + base + (size_t)q0 * D_MODEL;
    const __nv_bfloat16* Kh_g = kh + base;
    const __nv_bfloat16* Kl_g = kl + base;
    const __nv_bfloat16* Vh_g = vh + base;
    const __nv_bfloat16* Vl_g = vl + base;

    #pragma unroll
    for (int i = 0; i < 4; i++) {
        int e = t + i * 256;
        int row = e >> 3, seg = e & 7;
        uint32_t d = (uint32_t)(row * AT_RS + seg * 16);
        cp_async16(sb + d, Qh_g + (size_t)row * D_MODEL + seg * 8);
        cp_async16(sb + AT_Q_BYTES + d, Ql_g + (size_t)row * D_MODEL + seg * 8);
    }
    cp_commit();

    auto loadkv = [&](int c, int s) {
        const uint32_t st = sb + AT_KV_BASE + s * AT_STAGE;
        #pragma unroll
        for (int i = 0; i < 8; i++) {
            int e = t + i * 256;
            int arr = e >> 9, row = (e >> 3) & 63, seg = e & 7;
            const __nv_bfloat16* src =
                (arr == 0) ? Kh_g : (arr == 1) ? Kl_g : (arr == 2) ? Vh_g : Vl_g;
            cp_async16(st + arr * AT_ARR + (uint32_t)(row * AT_RS + seg * 16),
                       src + (size_t)(c * 64 + row) * D_MODEL + seg * 8);
        }
        cp_commit();
    };

    loadkv(0, 0);
    loadkv(1, 1);

    cp_wait_group<2>();
    __syncthreads();
    uint32_t qfh[4][4], qfl[4][4];
    {
        const uint32_t ab = sb + (uint32_t)(wid * 16 + (lane & 15)) * AT_RS
                          + (uint32_t)(lane >> 4) * 16;
        #pragma unroll
        for (int kk = 0; kk < 4; kk++) {
            ldsm4(qfh[kk][0], qfh[kk][1], qfh[kk][2], qfh[kk][3], ab + kk * 32);
            ldsm4(qfl[kk][0], qfl[kk][1], qfl[kk][2], qfl[kk][3], ab + AT_Q_BYTES + kk * 32);
        }
    }

    float accO[8][4] = {};
    float m0r = -1e30f, m1r = -1e30f, l0 = 0.f, l1 = 0.f;

    const uint32_t bb_off = (uint32_t)((lane & 7) + ((lane >> 4) << 3)) * AT_RS
                          + (uint32_t)((lane >> 3) & 1) * 16;
    const uint32_t vb_off = (uint32_t)(lane & 15) * AT_RS + (uint32_t)(lane >> 4) * 16;

    for (int c = 0; c < NKV; c++) {
        if (c + 1 < NKV) cp_wait_group<1>(); else cp_wait_group<0>();
        __syncthreads();
        if (c + 2 < NKV) loadkv(c + 2, (c + 2) % 3);

        const uint32_t st = sb + AT_KV_BASE + (c % 3) * AT_STAGE;

        float s[8][4] = {};
        #pragma unroll
        for (int kk = 0; kk < 4; kk++) {
            const uint32_t bk = st + bb_off + kk * 32;
            #pragma unroll
            for (int g = 0; g < 4; g++) {
                uint32_t r0, r1, r2, r3;
                ldsm4(r0, r1, r2, r3, bk + (uint32_t)g * 16 * AT_RS);
                uint32_t bh0[2] = {r0, r1}, bh1[2] = {r2, r3};
                mma16816(s[g * 2 + 0], qfh[kk], bh0);
                mma16816(s[g * 2 + 1], qfh[kk], bh1);
                mma16816(s[g * 2 + 0], qfl[kk], bh0);
                mma16816(s[g * 2 + 1], qfl[kk], bh1);
                ldsm4(r0, r1, r2, r3, bk + AT_ARR + (uint32_t)g * 16 * AT_RS);
                uint32_t bl0[2] = {r0, r1}, bl1[2] = {r2, r3};
                mma16816(s[g * 2 + 0], qfh[kk], bl0);
                mma16816(s[g * 2 + 1], qfh[kk], bl1);
            }
        }

        float mx0 = s[0][0], mx1 = s[0][2];
        #pragma unroll
        for (int j = 0; j < 8; j++) {
            mx0 = fmaxf(mx0, fmaxf(s[j][0], s[j][1]));
            mx1 = fmaxf(mx1, fmaxf(s[j][2], s[j][3]));
        }
        mx0 = fmaxf(mx0, __shfl_xor_sync(0xffffffffu, mx0, 1));
        mx0 = fmaxf(mx0, __shfl_xor_sync(0xffffffffu, mx0, 2));
        mx1 = fmaxf(mx1, __shfl_xor_sync(0xffffffffu, mx1, 1));
        mx1 = fmaxf(mx1, __shfl_xor_sync(0xffffffffu, mx1, 2));

        const float mn0 = fmaxf(m0r, mx0), mn1 = fmaxf(m1r, mx1);
        const float al0 = __expf(m0r - mn0), al1 = __expf(m1r - mn1);
        m0r = mn0; m1r = mn1;

        float rs0 = 0.f, rs1 = 0.f;
        #pragma unroll
        for (int j = 0; j < 8; j++) {
            s[j][0] = __expf(s[j][0] - mn0);
            s[j][1] = __expf(s[j][1] - mn0);
            s[j][2] = __expf(s[j][2] - mn1);
            s[j][3] = __expf(s[j][3] - mn1);
            rs0 += s[j][0] + s[j][1];
            rs1 += s[j][2] + s[j][3];
        }
        rs0 += __shfl_xor_sync(0xffffffffu, rs0, 1);
        rs0 += __shfl_xor_sync(0xffffffffu, rs0, 2);
        rs1 += __shfl_xor_sync(0xffffffffu, rs1, 1);
        rs1 += __shfl_xor_sync(0xffffffffu, rs1, 2);
        l0 = l0 * al0 + rs0;
        l1 = l1 * al1 + rs1;

        #pragma unroll
        for (int nt = 0; nt < 8; nt++) {
            accO[nt][0] *= al0; accO[nt][1] *= al0;
            accO[nt][2] *= al1; accO[nt][3] *= al1;
        }

        uint32_t ph[4][4], pl[4][4];
        #pragma unroll
        for (int kk = 0; kk < 4; kk++) {
            const int j0 = 2 * kk, j1 = 2 * kk + 1;
            float v00 = s[j0][0], v01 = s[j0][1], v02 = s[j0][2], v03 = s[j0][3];
            float v10 = s[j1][0], v11 = s[j1][1], v12 = s[j1][2], v13 = s[j1][3];
            __nv_bfloat16 h;
            float r00, r01, r02, r03, r10, r11, r12, r13;
            h = __float2bfloat16(v00); r00 = v00 - __bfloat162float(h);
            h = __float2bfloat16(v01); r01 = v01 - __bfloat162float(h);
            h = __float2bfloat16(v02); r02 = v02 - __bfloat162float(h);
            h = __float2bfloat16(v03); r03 = v03 - __bfloat162float(h);
            h = __float2bfloat16(v10); r10 = v10 - __bfloat162float(h);
            h = __float2bfloat16(v11); r11 = v11 - __bfloat162float(h);
            h = __float2bfloat16(v12); r12 = v12 - __bfloat162float(h);
            h = __float2bfloat16(v13); r13 = v13 - __bfloat162float(h);
            ph[kk][0] = pack_bf16(v00, v01);
            ph[kk][1] = pack_bf16(v02, v03);
            ph[kk][2] = pack_bf16(v10, v11);
            ph[kk][3] = pack_bf16(v12, v13);
            pl[kk][0] = pack_bf16(r00, r01);
            pl[kk][1] = pack_bf16(r02, r03);
            pl[kk][2] = pack_bf16(r10, r11);
            pl[kk][3] = pack_bf16(r12, r13);
        }

        const uint32_t vst = st + 2 * AT_ARR;
        #pragma unroll
        for (int kk = 0; kk < 4; kk++) {
            const uint32_t vk = vst + vb_off + (uint32_t)(kk * 16) * AT_RS;
            #pragma unroll
            for (int np = 0; np < 4; np++) {
                uint32_t r0, r1, r2, r3;
                ldsm4t(r0, r1, r2, r3, vk + np * 32);
                uint32_t b0[2] = {r0, r1}, b1[2] = {r2, r3};
                mma16816(accO[np * 2 + 0], ph[kk], b0);
                mma16816(accO[np * 2 + 1], ph[kk], b1);
                mma16816(accO[np * 2 + 0], pl[kk], b0);
                mma16816(accO[np * 2 + 1], pl[kk], b1);
                ldsm4t(r0, r1, r2, r3, vk + AT_ARR + np * 32);
                uint32_t c0[2] = {r0, r1}, c1[2] = {r2, r3};
                mma16816(accO[np * 2 + 0], ph[kk], c0);
                mma16816(accO[np * 2 + 1], ph[kk], c1);
            }
        }
    }

    const float inv0 = 1.0f / l0, inv1 = 1.0f / l1;
    const int r0g = q0 + wid * 16 + (lane >> 2);
    const size_t orow0 = ((size_t)b * SEQ + r0g) * D_MODEL + h * D_K;
    const size_t orow1 = orow0 + 8 * D_MODEL;
    #pragma unroll
    for (int nt = 0; nt < 8; nt++) {
        const int col = nt * 8 + (lane & 3) * 2;
        float o00 = accO[nt][0] * inv0, o01 = accO[nt][1] * inv0;
        float o10 = accO[nt][2] * inv1, o11 = accO[nt][3] * inv1;
        __nv_bfloat16 h00 = __float2bfloat16(o00), h01 = __float2bfloat16(o01);
        __nv_bfloat16 h10 = __float2bfloat16(o10), h11 = __float2bfloat16(o11);
        uint32_t hp0 = (uint32_t)__bfloat16_as_ushort(h00) | ((uint32_t)__bfloat16_as_ushort(h01) << 16);
        uint32_t hp1 = (uint32_t)__bfloat16_as_ushort(h10) | ((uint32_t)__bfloat16_as_ushort(h11) << 16);
        uint32_t lp0 = pack_bf16(o00 - __bfloat162float(h00), o01 - __bfloat162float(h01));
        uint32_t lp1 = pack_bf16(o10 - __bfloat162float(h10), o11 - __bfloat162float(h11));
        *reinterpret_cast<uint32_t*>(&Ch[orow0 + col]) = hp0;
        *reinterpret_cast<uint32_t*>(&Ch[orow1 + col]) = hp1;
        *reinterpret_cast<uint32_t*>(&Cl[orow0 + col]) = lp0;
        *reinterpret_cast<uint32_t*>(&Cl[orow1 + col]) = lp1;
    }
}

// ---------------------------------------------------------------------------
// Launch
// ---------------------------------------------------------------------------
extern "C" void kernel_launch(void* const* d_in, const int* in_sizes, int n_in,
                              void* d_out, int out_size)
{
    const float* q   = (const float*)d_in[0];
    const float* k   = (const float*)d_in[1];
    const float* v   = (const float*)d_in[2];
    const float* w_q = (const float*)d_in[3];
    const float* b_q = (const float*)d_in[4];
    const float* w_k = (const float*)d_in[5];
    const float* b_k = (const float*)d_in[6];
    const float* w_v = (const float*)d_in[7];
    const float* b_v = (const float*)d_in[8];
    const float* w_o = (const float*)d_in[9];
    const float* b_o = (const float*)d_in[10];
    float* out = (float*)d_out;

    __nv_bfloat16 *xh, *xl, *wh, *wl, *qh, *ql, *kh, *kl, *vh, *vl;
    cudaGetSymbolAddress((void**)&xh, g_xh);
    cudaGetSymbolAddress((void**)&xl, g_xl);
    cudaGetSymbolAddress((void**)&wh, g_wh);
    cudaGetSymbolAddress((void**)&wl, g_wl);
    cudaGetSymbolAddress((void**)&qh, g_qh);
    cudaGetSymbolAddress((void**)&ql, g_ql);
    cudaGetSymbolAddress((void**)&kh, g_kh);
    cudaGetSymbolAddress((void**)&kl, g_kl);
    cudaGetSymbolAddress((void**)&vh, g_vh);
    cudaGetSymbolAddress((void**)&vl, g_vl);

    cudaFuncSetAttribute(gemm_mma,
                         cudaFuncAttributeMaxDynamicSharedMemorySize, GEMM_SMEM);
    cudaFuncSetAttribute(attn_mma,
                         cudaFuncAttributeMaxDynamicSharedMemorySize, AT_SMEM);

    const int gx = NX / 16 / 256;               // 768
    const int gw = NW / 16 / 256;               // 144

    // All splits up front (2 launches)
    split_w_kernel<<<dim3(gw, 4), 256>>>(w_q, w_k, w_v, w_o);
    split_x_kernel<<<dim3(gx, 3), 256>>>(q, k, v);

    // Fused Q/K/V projections (z = 0,1,2); scale folded into Q
    dim3 qkv_grid(D_MODEL / 128, M_ROWS / 128, 3);  // (6, 32, 3)
    gemm_mma<<<qkv_grid, 256, GEMM_SMEM>>>(
        xh, xl, wh, wl, b_q, b_k, b_v,
        qh, kh, vh, ql, kl, vl, nullptr, 0.125f);

    // Attention (writes split ctx into x slot 0)
    dim3 attn_grid(SEQ / 128, NUM_HEADS, BATCH);  // (16, 12, 2)
    attn_mma<<<attn_grid, 256, AT_SMEM>>>(qh, ql, kh, kl, vh, vl, xh, xl);

    // Output projection (weight slot 3) -> fp32 out
    dim3 out_grid(D_MODEL / 128, M_ROWS / 128, 1);
    gemm_mma<<<out_grid, 256, GEMM_SMEM>>>(
        xh, xl, wh + (size_t)3 * NW, wl + (size_t)3 * NW, b_o, b_o, b_o,
        nullptr, nullptr, nullptr, nullptr, nullptr, nullptr, out, 1.0f);
}

// round 11
// speedup vs baseline: 1.0308x; 1.0306x over previous
#include <cuda_runtime.h>
#include <cuda_bf16.h>
#include <cstdint>

#define D_MODEL 768
#define NUM_HEADS 12
#define D_K 64
#define BATCH 2
#define SEQ 2048
#define M_ROWS (BATCH * SEQ)   // 4096
#define NX (M_ROWS * D_MODEL)  // 3145728
#define NW (D_MODEL * D_MODEL) // 589824

// ---------------------------------------------------------------------------
// Scratch (__device__ globals; allocation-free rule)
// ---------------------------------------------------------------------------
__device__ __nv_bfloat16 g_xh[3 * NX];   // split q,k,v inputs; slot0 reused for ctx
__device__ __nv_bfloat16 g_xl[3 * NX];
__device__ __nv_bfloat16 g_wh[4 * NW];   // split w_q,w_k,w_v,w_o
__device__ __nv_bfloat16 g_wl[4 * NW];
__device__ __nv_bfloat16 g_qh[NX];
__device__ __nv_bfloat16 g_ql[NX];
__device__ __nv_bfloat16 g_kh[NX];
__device__ __nv_bfloat16 g_kl[NX];
__device__ __nv_bfloat16 g_vh[NX];
__device__ __nv_bfloat16 g_vl[NX];

// ---------------------------------------------------------------------------
// PTX helpers (family-target safe)
// ---------------------------------------------------------------------------
__device__ __forceinline__ uint32_t smem_to_u32(const void* p) {
    uint32_t a;
    asm("{ .reg .u64 t; cvta.to.shared.u64 t, %1; cvt.u32.u64 %0, t; }"
        : "=r"(a) : "l"(p));
    return a;
}
__device__ __forceinline__ void cp_async16(uint32_t dst, const void* src) {
    asm volatile("cp.async.cg.shared.global [%0], [%1], 16;" :: "r"(dst), "l"(src));
}
__device__ __forceinline__ void cp_commit() {
    asm volatile("cp.async.commit_group;" ::: "memory");
}
template <int N>
__device__ __forceinline__ void cp_wait_group() {
    asm volatile("cp.async.wait_group %0;" :: "n"(N) : "memory");
}
__device__ __forceinline__ void ldsm4(uint32_t& r0, uint32_t& r1, uint32_t& r2,
                                      uint32_t& r3, uint32_t addr) {
    asm volatile("ldmatrix.sync.aligned.m8n8.x4.shared.b16 {%0,%1,%2,%3}, [%4];"
                 : "=r"(r0), "=r"(r1), "=r"(r2), "=r"(r3) : "r"(addr));
}
__device__ __forceinline__ void ldsm4t(uint32_t& r0, uint32_t& r1, uint32_t& r2,
                                       uint32_t& r3, uint32_t addr) {
    asm volatile("ldmatrix.sync.aligned.m8n8.x4.trans.shared.b16 {%0,%1,%2,%3}, [%4];"
                 : "=r"(r0), "=r"(r1), "=r"(r2), "=r"(r3) : "r"(addr));
}
__device__ __forceinline__ void mma16816(float* d, const uint32_t* a, const uint32_t* b) {
    asm volatile(
        "mma.sync.aligned.m16n8k16.row.col.f32.bf16.bf16.f32 "
        "{%0,%1,%2,%3}, {%4,%5,%6,%7}, {%8,%9}, {%0,%1,%2,%3};"
        : "+f"(d[0]), "+f"(d[1]), "+f"(d[2]), "+f"(d[3])
        : "r"(a[0]), "r"(a[1]), "r"(a[2]), "r"(a[3]), "r"(b[0]), "r"(b[1]));
}
__device__ __forceinline__ uint32_t pack_bf16(float x, float y) {
    __nv_bfloat16 bx = __float2bfloat16(x), by = __float2bfloat16(y);
    return (uint32_t)__bfloat16_as_ushort(bx) | ((uint32_t)__bfloat16_as_ushort(by) << 16);
}

// ---------------------------------------------------------------------------
// Split fp32 -> (bf16 hi, bf16 lo); z selects source/dest (fused launches)
// ---------------------------------------------------------------------------
__device__ __forceinline__ void split16(const float* __restrict__ x,
                                        __nv_bfloat16* __restrict__ hi,
                                        __nv_bfloat16* __restrict__ lo, int i0)
{
    float4 v[4];
    #pragma unroll
    for (int u = 0; u < 4; u++)
        v[u] = *reinterpret_cast<const float4*>(x + i0 + u * 4);
    #pragma unroll
    for (int u = 0; u < 4; u++) {
        float vs[4] = {v[u].x, v[u].y, v[u].z, v[u].w};
        uint32_t hp[2], lp[2];
        #pragma unroll
        for (int p = 0; p < 2; p++) {
            __nv_bfloat16 h0 = __float2bfloat16(vs[p * 2 + 0]);
            __nv_bfloat16 h1 = __float2bfloat16(vs[p * 2 + 1]);
            __nv_bfloat16 l0 = __float2bfloat16(vs[p * 2 + 0] - __bfloat162float(h0));
            __nv_bfloat16 l1 = __float2bfloat16(vs[p * 2 + 1] - __bfloat162float(h1));
            hp[p] = (uint32_t)__bfloat16_as_ushort(h0) | ((uint32_t)__bfloat16_as_ushort(h1) << 16);
            lp[p] = (uint32_t)__bfloat16_as_ushort(l0) | ((uint32_t)__bfloat16_as_ushort(l1) << 16);
        }
        *reinterpret_cast<uint2*>(hi + i0 + u * 4) = make_uint2(hp[0], hp[1]);
        *reinterpret_cast<uint2*>(lo + i0 + u * 4) = make_uint2(lp[0], lp[1]);
    }
}

__global__ __launch_bounds__(256) void split_w_kernel(
    const float* __restrict__ w0, const float* __restrict__ w1,
    const float* __restrict__ w2, const float* __restrict__ w3)
{
    const int z = blockIdx.y;
    const float* src = (z == 0) ? w0 : (z == 1) ? w1 : (z == 2) ? w2 : w3;
    const int i0 = (blockIdx.x * 256 + threadIdx.x) * 16;
    if (i0 >= NW) return;
    split16(src, g_wh + (size_t)z * NW, g_wl + (size_t)z * NW, i0);
}

__global__ __launch_bounds__(256) void split_x_kernel(
    const float* __restrict__ x0, const float* __restrict__ x1,
    const float* __restrict__ x2)
{
    const int z = blockIdx.y;
    const float* src = (z == 0) ? x0 : (z == 1) ? x1 : x2;
    const int i0 = (blockIdx.x * 256 + threadIdx.x) * 16;
    if (i0 >= NX) return;
    split16(src, g_xh + (size_t)z * NX, g_xl + (size_t)z * NX, i0);
}

// ---------------------------------------------------------------------------
// Fused split-precision GEMM, z-fused over projections (unchanged from R7/R10).
// ---------------------------------------------------------------------------
#define BK 32
#define SMEM_STRIDE 80
#define ARR_BYTES (128 * SMEM_STRIDE)      // 10240
#define STAGE_BYTES (4 * ARR_BYTES)        // 40960
#define GEMM_SMEM (2 * STAGE_BYTES)        // 81920
#define NCHUNK (D_MODEL / BK)              // 24

__global__ __launch_bounds__(256, 2) void gemm_mma(
    const __nv_bfloat16* __restrict__ XH, const __nv_bfloat16* __restrict__ XL,
    const __nv_bfloat16* __restrict__ WH, const __nv_bfloat16* __restrict__ WL,
    const float* __restrict__ b0, const float* __restrict__ b1,
    const float* __restrict__ b2,
    __nv_bfloat16* __restrict__ yh0, __nv_bfloat16* __restrict__ yh1,
    __nv_bfloat16* __restrict__ yh2,
    __nv_bfloat16* __restrict__ yl0, __nv_bfloat16* __restrict__ yl1,
    __nv_bfloat16* __restrict__ yl2,
    float* __restrict__ Yf, float scale0)
{
    extern __shared__ __align__(128) char smem[];
    const uint32_t sb = smem_to_u32(smem);
    const int z    = blockIdx.z;
    const int t    = threadIdx.x;
    const int wid  = t >> 5;
    const int lane = t & 31;
    const int warp_m = wid & 1;
    const int warp_n = wid >> 1;
    const int n0 = blockIdx.x * 128;
    const int m0 = blockIdx.y * 128;

    const __nv_bfloat16* Ah = XH + (size_t)z * NX;
    const __nv_bfloat16* Al = XL + (size_t)z * NX;
    const __nv_bfloat16* Bh = WH + (size_t)z * NW;
    const __nv_bfloat16* Bl = WL + (size_t)z * NW;
    const float* bias = (z == 0) ? b0 : (z == 1) ? b1 : b2;
    __nv_bfloat16* Yh = (z == 0) ? yh0 : (z == 1) ? yh1 : yh2;
    __nv_bfloat16* Yl = (z == 0) ? yl0 : (z == 1) ? yl1 : yl2;
    const float scale = (z == 0) ? scale0 : 1.0f;

    const uint32_t a_off = (uint32_t)(warp_m * 64 + (lane & 15)) * SMEM_STRIDE
                         + (uint32_t)(lane >> 4) * 16;
    const uint32_t b_off = (uint32_t)(warp_n * 32 + (lane & 7) + ((lane >> 4) << 3)) * SMEM_STRIDE
                         + (uint32_t)((lane >> 3) & 1) * 16;

    float acc[4][4][4] = {};

    auto load_chunk = [&](int c, int s) {
        const int k0 = c * BK;
        const uint32_t base = sb + s * STAGE_BYTES;
        #pragma unroll
        for (int i = 0; i < 8; i++) {
            const int e = t + i * 256;
            const int arr = e >> 9;
            const int row = (e >> 2) & 127;
            const int seg = e & 3;
            const __nv_bfloat16* src =
                (arr == 0) ? (Ah + (size_t)(m0 + row) * D_MODEL) :
                (arr == 1) ? (Al + (size_t)(m0 + row) * D_MODEL) :
                (arr == 2) ? (Bh + (size_t)(n0 + row) * D_MODEL) :
                             (Bl + (size_t)(n0 + row) * D_MODEL);
            cp_async16(base + (uint32_t)arr * ARR_BYTES
                            + (uint32_t)(row * SMEM_STRIDE + seg * 16),
                       src + k0 + seg * 8);
        }
        cp_commit();
    };

    load_chunk(0, 0);

    for (int c = 0; c < NCHUNK; c++) {
        __syncthreads();
        if (c + 1 < NCHUNK) {
            load_chunk(c + 1, (c + 1) & 1);
            cp_wait_group<1>();
        } else {
            cp_wait_group<0>();
        }
        __syncthreads();

        const uint32_t st = sb + (c & 1) * STAGE_BYTES;

        #pragma unroll
        for (int ks = 0; ks < 2; ks++) {
            uint32_t bh[4][2], bl[4][2];
            #pragma unroll
            for (int p = 0; p < 2; p++) {
                uint32_t r0, r1, r2, r3;
                ldsm4(r0, r1, r2, r3,
                      st + 2 * ARR_BYTES + b_off + p * 16 * SMEM_STRIDE + ks * 32);
                bh[p * 2 + 0][0] = r0; bh[p * 2 + 0][1] = r1;
                bh[p * 2 + 1][0] = r2; bh[p * 2 + 1][1] = r3;
                ldsm4(r0, r1, r2, r3,
                      st + 3 * ARR_BYTES + b_off + p * 16 * SMEM_STRIDE + ks * 32);
                bl[p * 2 + 0][0] = r0; bl[p * 2 + 0][1] = r1;
                bl[p * 2 + 1][0] = r2; bl[p * 2 + 1][1] = r3;
            }
            {
                uint32_t af[4][4];
                #pragma unroll
                for (int mt = 0; mt < 4; mt++)
                    ldsm4(af[mt][0], af[mt][1], af[mt][2], af[mt][3],
                          st + a_off + mt * 16 * SMEM_STRIDE + ks * 32);
                #pragma unroll
                for (int mt = 0; mt < 4; mt++)
                    #pragma unroll
                    for (int nt = 0; nt < 4; nt++) {
                        mma16816(acc[mt][nt], af[mt], bh[nt]);
                        mma16816(acc[mt][nt], af[mt], bl[nt]);
                    }
            }
            {
                uint32_t al[4][4];
                #pragma unroll
                for (int mt = 0; mt < 4; mt++)
                    ldsm4(al[mt][0], al[mt][1], al[mt][2], al[mt][3],
                          st + ARR_BYTES + a_off + mt * 16 * SMEM_STRIDE + ks * 32);
                #pragma unroll
                for (int mt = 0; mt < 4; mt++)
                    #pragma unroll
                    for (int nt = 0; nt < 4; nt++)
                        mma16816(acc[mt][nt], al[mt], bh[nt]);
            }
        }
    }

    const int colb = n0 + warp_n * 32 + (lane & 3) * 2;
    const int rowb = m0 + warp_m * 64 + (lane >> 2);
    #pragma unroll
    for (int nt = 0; nt < 4; nt++) {
        const int col = colb + nt * 8;
        const float2 bv = *reinterpret_cast<const float2*>(&bias[col]);
        #pragma unroll
        for (int mt = 0; mt < 4; mt++) {
            const int r0 = rowb + mt * 16;
            float o00 = acc[mt][nt][0] + bv.x, o01 = acc[mt][nt][1] + bv.y;
            float o10 = acc[mt][nt][2] + bv.x, o11 = acc[mt][nt][3] + bv.y;
            if (Yf) {
                *reinterpret_cast<float2*>(&Yf[(size_t)r0 * D_MODEL + col]) = make_float2(o00, o01);
                *reinterpret_cast<float2*>(&Yf[(size_t)(r0 + 8) * D_MODEL + col]) = make_float2(o10, o11);
            } else {
                o00 *= scale; o01 *= scale; o10 *= scale; o11 *= scale;
                __nv_bfloat16 h00 = __float2bfloat16(o00), h01 = __float2bfloat16(o01);
                __nv_bfloat16 h10 = __float2bfloat16(o10), h11 = __float2bfloat16(o11);
                uint32_t hp0 = (uint32_t)__bfloat16_as_ushort(h00) | ((uint32_t)__bfloat16_as_ushort(h01) << 16);
                uint32_t hp1 = (uint32_t)__bfloat16_as_ushort(h10) | ((uint32_t)__bfloat16_as_ushort(h11) << 16);
                uint32_t lp0 = pack_bf16(o00 - __bfloat162float(h00), o01 - __bfloat162float(h01));
                uint32_t lp1 = pack_bf16(o10 - __bfloat162float(h10), o11 - __bfloat162float(h11));
                *reinterpret_cast<uint32_t*>(&Yh[(size_t)r0 * D_MODEL + col]) = hp0;
                *reinterpret_cast<uint32_t*>(&Yh[(size_t)(r0 + 8) * D_MODEL + col]) = hp1;
                *reinterpret_cast<uint32_t*>(&Yl[(size_t)r0 * D_MODEL + col]) = lp0;
                *reinterpret_cast<uint32_t*>(&Yl[(size_t)(r0 + 8) * D_MODEL + col]) = lp1;
            }
        }
    }
}

// ---------------------------------------------------------------------------
// FA2-style attention, mma.sync bf16 3-term split.
// R11 changes: 2-stage KV pipeline (smem 110.6KB -> 2 CTAs/SM),
// Q fragments re-loaded from smem per chunk (saves 32 regs),
// __launch_bounds__(256,2) to cap regs at 128.
// ---------------------------------------------------------------------------
#define AT_RS 144
#define AT_Q_BYTES (128 * AT_RS)        // 18432
#define AT_ARR (64 * AT_RS)             // 9216
#define AT_STAGE (4 * AT_ARR)           // 36864
#define AT_KV_BASE (2 * AT_Q_BYTES)     // 36864
#define AT_SMEM (AT_KV_BASE + 2 * AT_STAGE)  // 110592
#define NKV (SEQ / 64)                  // 32

__global__ __launch_bounds__(256, 2) void attn_mma(
    const __nv_bfloat16* __restrict__ qh, const __nv_bfloat16* __restrict__ ql,
    const __nv_bfloat16* __restrict__ kh, const __nv_bfloat16* __restrict__ kl,
    const __nv_bfloat16* __restrict__ vh, const __nv_bfloat16* __restrict__ vl,
    __nv_bfloat16* __restrict__ Ch, __nv_bfloat16* __restrict__ Cl)
{
    extern __shared__ __align__(128) char smem[];
    const uint32_t sb = smem_to_u32(smem);
    const int t    = threadIdx.x;
    const int wid  = t >> 5;
    const int lane = t & 31;
    const int b  = blockIdx.z;
    const int h  = blockIdx.y;
    const int q0 = blockIdx.x * 128;

    const size_t base = (size_t)b * SEQ * D_MODEL + h * D_K;
    const __nv_bfloat16* Qh_g = qh + base + (size_t)q0 * D_MODEL;
    const __nv_bfloat16* Ql_g = ql + base + (size_t)q0 * D_MODEL;
    const __nv_bfloat16* Kh_g = kh + base;
    const __nv_bfloat16* Kl_g = kl + base;
    const __nv_bfloat16* Vh_g = vh + base;
    const __nv_bfloat16* Vl_g = vl + base;

    #pragma unroll
    for (int i = 0; i < 4; i++) {
        int e = t + i * 256;
        int row = e >> 3, seg = e & 7;
        uint32_t d = (uint32_t)(row * AT_RS + seg * 16);
        cp_async16(sb + d, Qh_g + (size_t)row * D_MODEL + seg * 8);
        cp_async16(sb + AT_Q_BYTES + d, Ql_g + (size_t)row * D_MODEL + seg * 8);
    }
    cp_commit();

    auto loadkv = [&](int c, int s) {
        const uint32_t st = sb + AT_KV_BASE + s * AT_STAGE;
        #pragma unroll
        for (int i = 0; i < 8; i++) {
            int e = t + i * 256;
            int arr = e >> 9, row = (e >> 3) & 63, seg = e & 7;
            const __nv_bfloat16* src =
                (arr == 0) ? Kh_g : (arr == 1) ? Kl_g : (arr == 2) ? Vh_g : Vl_g;
            cp_async16(st + arr * AT_ARR + (uint32_t)(row * AT_RS + seg * 16),
                       src + (size_t)(c * 64 + row) * D_MODEL + seg * 8);
        }
        cp_commit();
    };

    loadkv(0, 0);

    // Q ldmatrix base (per-warp, reused every chunk)
    const uint32_t qab = sb + (uint32_t)(wid * 16 + (lane & 15)) * AT_RS
                       + (uint32_t)(lane >> 4) * 16;

    float accO[8][4] = {};
    float m0r = -1e30f, m1r = -1e30f, l0 = 0.f, l1 = 0.f;

    const uint32_t bb_off = (uint32_t)((lane & 7) + ((lane >> 4) << 3)) * AT_RS
                          + (uint32_t)((lane >> 3) & 1) * 16;
    const uint32_t vb_off = (uint32_t)(lane & 15) * AT_RS + (uint32_t)(lane >> 4) * 16;

    for (int c = 0; c < NKV; c++) {
        __syncthreads();   // all warps done reading stage (c+1)&1 (from iter c-1)
        if (c + 1 < NKV) {
            loadkv(c + 1, (c + 1) & 1);
            cp_wait_group<1>();
        } else {
            cp_wait_group<0>();
        }
        __syncthreads();   // stage c&1 (and Q on c==0) visible

        const uint32_t st = sb + AT_KV_BASE + (c & 1) * AT_STAGE;

        // ---- S = Qh*Kh + Ql*Kh + Qh*Kl (Q frags from smem per kk) ----
        float s[8][4] = {};
        #pragma unroll
        for (int kk = 0; kk < 4; kk++) {
            uint32_t qfh[4], qfl[4];
            ldsm4(qfh[0], qfh[1], qfh[2], qfh[3], qab + kk * 32);
            ldsm4(qfl[0], qfl[1], qfl[2], qfl[3], qab + AT_Q_BYTES + kk * 32);
            const uint32_t bk = st + bb_off + kk * 32;
            #pragma unroll
            for (int g = 0; g < 4; g++) {
                uint32_t r0, r1, r2, r3;
                ldsm4(r0, r1, r2, r3, bk + (uint32_t)g * 16 * AT_RS);
                uint32_t bh0[2] = {r0, r1}, bh1[2] = {r2, r3};
                mma16816(s[g * 2 + 0], qfh, bh0);
                mma16816(s[g * 2 + 1], qfh, bh1);
                mma16816(s[g * 2 + 0], qfl, bh0);
                mma16816(s[g * 2 + 1], qfl, bh1);
                ldsm4(r0, r1, r2, r3, bk + AT_ARR + (uint32_t)g * 16 * AT_RS);
                uint32_t bl0[2] = {r0, r1}, bl1[2] = {r2, r3};
                mma16816(s[g * 2 + 0], qfh, bl0);
                mma16816(s[g * 2 + 1], qfh, bl1);
            }
        }

        // ---- online softmax ----
        float mx0 = s[0][0], mx1 = s[0][2];
        #pragma unroll
        for (int j = 0; j < 8; j++) {
            mx0 = fmaxf(mx0, fmaxf(s[j][0], s[j][1]));
            mx1 = fmaxf(mx1, fmaxf(s[j][2], s[j][3]));
        }
        mx0 = fmaxf(mx0, __shfl_xor_sync(0xffffffffu, mx0, 1));
        mx0 = fmaxf(mx0, __shfl_xor_sync(0xffffffffu, mx0, 2));
        mx1 = fmaxf(mx1, __shfl_xor_sync(0xffffffffu, mx1, 1));
        mx1 = fmaxf(mx1, __shfl_xor_sync(0xffffffffu, mx1, 2));

        const float mn0 = fmaxf(m0r, mx0), mn1 = fmaxf(m1r, mx1);
        const float al0 = __expf(m0r - mn0), al1 = __expf(m1r - mn1);
        m0r = mn0; m1r = mn1;

        float rs0 = 0.f, rs1 = 0.f;
        #pragma unroll
        for (int j = 0; j < 8; j++) {
            s[j][0] = __expf(s[j][0] - mn0);
            s[j][1] = __expf(s[j][1] - mn0);
            s[j][2] = __expf(s[j][2] - mn1);
            s[j][3] = __expf(s[j][3] - mn1);
            rs0 += s[j][0] + s[j][1];
            rs1 += s[j][2] + s[j][3];
        }
        rs0 += __shfl_xor_sync(0xffffffffu, rs0, 1);
        rs0 += __shfl_xor_sync(0xffffffffu, rs0, 2);
        rs1 += __shfl_xor_sync(0xffffffffu, rs1, 1);
        rs1 += __shfl_xor_sync(0xffffffffu, rs1, 2);
        l0 = l0 * al0 + rs0;
        l1 = l1 * al1 + rs1;

        #pragma unroll
        for (int nt = 0; nt < 8; nt++) {
            accO[nt][0] *= al0; accO[nt][1] *= al0;
            accO[nt][2] *= al1; accO[nt][3] *= al1;
        }

        // ---- P -> bf16 hi/lo fragments ----
        uint32_t ph[4][4], pl[4][4];
        #pragma unroll
        for (int kk = 0; kk < 4; kk++) {
            const int j0 = 2 * kk, j1 = 2 * kk + 1;
            float v00 = s[j0][0], v01 = s[j0][1], v02 = s[j0][2], v03 = s[j0][3];
            float v10 = s[j1][0], v11 = s[j1][1], v12 = s[j1][2], v13 = s[j1][3];
            __nv_bfloat16 h;
            float r00, r01, r02, r03, r10, r11, r12, r13;
            h = __float2bfloat16(v00); r00 = v00 - __bfloat162float(h);
            h = __float2bfloat16(v01); r01 = v01 - __bfloat162float(h);
            h = __float2bfloat16(v02); r02 = v02 - __bfloat162float(h);
            h = __float2bfloat16(v03); r03 = v03 - __bfloat162float(h);
            h = __float2bfloat16(v10); r10 = v10 - __bfloat162float(h);
            h = __float2bfloat16(v11); r11 = v11 - __bfloat162float(h);
            h = __float2bfloat16(v12); r12 = v12 - __bfloat162float(h);
            h = __float2bfloat16(v13); r13 = v13 - __bfloat162float(h);
            ph[kk][0] = pack_bf16(v00, v01);
            ph[kk][1] = pack_bf16(v02, v03);
            ph[kk][2] = pack_bf16(v10, v11);
            ph[kk][3] = pack_bf16(v12, v13);
            pl[kk][0] = pack_bf16(r00, r01);
            pl[kk][1] = pack_bf16(r02, r03);
            pl[kk][2] = pack_bf16(r10, r11);
            pl[kk][3] = pack_bf16(r12, r13);
        }

        // ---- O += Ph*Vh + Pl*Vh + Ph*Vl ----
        const uint32_t vst = st + 2 * AT_ARR;
        #pragma unroll
        for (int kk = 0; kk < 4; kk++) {
            const uint32_t vk = vst + vb_off + (uint32_t)(kk * 16) * AT_RS;
            #pragma unroll
            for (int np = 0; np < 4; np++) {
                uint32_t r0, r1, r2, r3;
                ldsm4t(r0, r1, r2, r3, vk + np * 32);
                uint32_t b0[2] = {r0, r1}, b1[2] = {r2, r3};
                mma16816(accO[np * 2 + 0], ph[kk], b0);
                mma16816(accO[np * 2 + 1], ph[kk], b1);
                mma16816(accO[np * 2 + 0], pl[kk], b0);
                mma16816(accO[np * 2 + 1], pl[kk], b1);
                ldsm4t(r0, r1, r2, r3, vk + AT_ARR + np * 32);
                uint32_t c0[2] = {r0, r1}, c1[2] = {r2, r3};
                mma16816(accO[np * 2 + 0], ph[kk], c0);
                mma16816(accO[np * 2 + 1], ph[kk], c1);
            }
        }
    }

    const float inv0 = 1.0f / l0, inv1 = 1.0f / l1;
    const int r0g = q0 + wid * 16 + (lane >> 2);
    const size_t orow0 = ((size_t)b * SEQ + r0g) * D_MODEL + h * D_K;
    const size_t orow1 = orow0 + 8 * D_MODEL;
    #pragma unroll
    for (int nt = 0; nt < 8; nt++) {
        const int col = nt * 8 + (lane & 3) * 2;
        float o00 = accO[nt][0] * inv0, o01 = accO[nt][1] * inv0;
        float o10 = accO[nt][2] * inv1, o11 = accO[nt][3] * inv1;
        __nv_bfloat16 h00 = __float2bfloat16(o00), h01 = __float2bfloat16(o01);
        __nv_bfloat16 h10 = __float2bfloat16(o10), h11 = __float2bfloat16(o11);
        uint32_t hp0 = (uint32_t)__bfloat16_as_ushort(h00) | ((uint32_t)__bfloat16_as_ushort(h01) << 16);
        uint32_t hp1 = (uint32_t)__bfloat16_as_ushort(h10) | ((uint32_t)__bfloat16_as_ushort(h11) << 16);
        uint32_t lp0 = pack_bf16(o00 - __bfloat162float(h00), o01 - __bfloat162float(h01));
        uint32_t lp1 = pack_bf16(o10 - __bfloat162float(h10), o11 - __bfloat162float(h11));
        *reinterpret_cast<uint32_t*>(&Ch[orow0 + col]) = hp0;
        *reinterpret_cast<uint32_t*>(&Ch[orow1 + col]) = hp1;
        *reinterpret_cast<uint32_t*>(&Cl[orow0 + col]) = lp0;
        *reinterpret_cast<uint32_t*>(&Cl[orow1 + col]) = lp1;
    }
}

// ---------------------------------------------------------------------------
// Launch
// ---------------------------------------------------------------------------
extern "C" void kernel_launch(void* const* d_in, const int* in_sizes, int n_in,
                              void* d_out, int out_size)
{
    const float* q   = (const float*)d_in[0];
    const float* k   = (const float*)d_in[1];
    const float* v   = (const float*)d_in[2];
    const float* w_q = (const float*)d_in[3];
    const float* b_q = (const float*)d_in[4];
    const float* w_k = (const float*)d_in[5];
    const float* b_k = (const float*)d_in[6];
    const float* w_v = (const float*)d_in[7];
    const float* b_v = (const float*)d_in[8];
    const float* w_o = (const float*)d_in[9];
    const float* b_o = (const float*)d_in[10];
    float* out = (float*)d_out;

    __nv_bfloat16 *xh, *xl, *wh, *wl, *qh, *ql, *kh, *kl, *vh, *vl;
    cudaGetSymbolAddress((void**)&xh, g_xh);
    cudaGetSymbolAddress((void**)&xl, g_xl);
    cudaGetSymbolAddress((void**)&wh, g_wh);
    cudaGetSymbolAddress((void**)&wl, g_wl);
    cudaGetSymbolAddress((void**)&qh, g_qh);
    cudaGetSymbolAddress((void**)&ql, g_ql);
    cudaGetSymbolAddress((void**)&kh, g_kh);
    cudaGetSymbolAddress((void**)&kl, g_kl);
    cudaGetSymbolAddress((void**)&vh, g_vh);
    cudaGetSymbolAddress((void**)&vl, g_vl);

    cudaFuncSetAttribute(gemm_mma,
                         cudaFuncAttributeMaxDynamicSharedMemorySize, GEMM_SMEM);
    cudaFuncSetAttribute(attn_mma,
                         cudaFuncAttributeMaxDynamicSharedMemorySize, AT_SMEM);

    const int gx = NX / 16 / 256;               // 768
    const int gw = NW / 16 / 256;               // 144

    split_w_kernel<<<dim3(gw, 4), 256>>>(w_q, w_k, w_v, w_o);
    split_x_kernel<<<dim3(gx, 3), 256>>>(q, k, v);

    dim3 qkv_grid(D_MODEL / 128, M_ROWS / 128, 3);  // (6, 32, 3)
    gemm_mma<<<qkv_grid, 256, GEMM_SMEM>>>(
        xh, xl, wh, wl, b_q, b_k, b_v,
        qh, kh, vh, ql, kl, vl, nullptr, 0.125f);

    dim3 attn_grid(SEQ / 128, NUM_HEADS, BATCH);  // (16, 12, 2)
    attn_mma<<<attn_grid, 256, AT_SMEM>>>(qh, ql, kh, kl, vh, vl, xh, xl);

    dim3 out_grid(D_MODEL / 128, M_ROWS / 128, 1);
    gemm_mma<<<out_grid, 256, GEMM_SMEM>>>(
        xh, xl, wh + (size_t)3 * NW, wl + (size_t)3 * NW, b_o, b_o, b_o,
        nullptr, nullptr, nullptr, nullptr, nullptr, nullptr, out, 1.0f);
}